// round 14
// baseline (speedup 1.0000x reference)
#include <cuda_runtime.h>
#include <cuda_bf16.h>
#include <cstdint>

// ---------------- problem constants ----------------
#define BB      1024
#define S_OUT   30
#define S_IN    17
#define D_INN   3
#define HH      4
#define DKQ_I   6
#define DV_I    8
#define HID_I   256
#define OUT_I   64
#define HID_O   1024
#define OUT_O   1080

#define NU      (BB * S_OUT)          // 30720 inner units
#define CTXI_PER_U (HH * S_IN * DV_I) // 544
#define FC1I_M  (NU * HH)             // 122880
#define FC1I_K  (S_IN * DV_I)         // 136

// ---------------- scratch (device globals; no runtime allocation) -------------
__device__ float g_ctx  [(size_t)NU * CTXI_PER_U + 64];   // [122880][136]
__device__ float g_h1   [(size_t)FC1I_M * HID_I];         // [30720][1024]
__device__ float g_seq  [(size_t)NU * 64];                // [30720][64]
__device__ float g_wpackT[768 * 64];                      // [n=768][k=64] rounded
__device__ float g_bpack[768];
__device__ float g_qkv  [(size_t)NU * 768];               // [30720][768]
__device__ float g_ctxo [(size_t)BB * HH * S_OUT * 64];   // [4096][1920]
__device__ float g_h2   [(size_t)BB * HH * HID_O];        // [1024][4096]
__device__ float g_part [(size_t)4 * BB * OUT_O];         // split-K partials fc2_o
// transposed + tf32-rounded weights ([N][K])
__device__ float g_w1t[256 * 136];
__device__ float g_w2t[64 * 1024];
__device__ float g_w3t[1024 * 1920];
__device__ float g_w4t[1080 * 4096];

// ---------------- helpers ----------------
__device__ __forceinline__ float tanh_fast(float x) {
    float y; asm("tanh.approx.f32 %0, %1;" : "=f"(y) : "f"(x)); return y;
}
// round fp32 -> tf32 precision (RNA when followed by HW truncation of low 13 bits)
__device__ __forceinline__ float rnd_tf32(float f) {
    return __uint_as_float(__float_as_uint(f) + 0x1000u);
}
__device__ __forceinline__ uint32_t smem_u32(const void* p) {
    uint32_t a;
    asm("{ .reg .u64 t; cvta.to.shared.u64 t, %1; cvt.u32.u64 %0, t; }" : "=r"(a) : "l"(p));
    return a;
}
__device__ __forceinline__ void cp16(uint32_t dst, const void* src, int sz) {
    asm volatile("cp.async.cg.shared.global [%0], [%1], 16, %2;"
                 :: "r"(dst), "l"(src), "r"(sz) : "memory");
}
__device__ __forceinline__ void cp_commit() {
    asm volatile("cp.async.commit_group;" ::: "memory");
}
template<int N> __device__ __forceinline__ void cp_wait() {
    asm volatile("cp.async.wait_group %0;" :: "n"(N) : "memory");
}
__device__ __forceinline__ void mma_tf32(float c[4], uint32_t a0, uint32_t a1,
                                         uint32_t a2, uint32_t a3,
                                         uint32_t b0, uint32_t b1) {
    asm volatile(
        "mma.sync.aligned.m16n8k8.row.col.f32.tf32.tf32.f32 "
        "{%0,%1,%2,%3}, {%4,%5,%6,%7}, {%8,%9}, {%0,%1,%2,%3};"
        : "+f"(c[0]), "+f"(c[1]), "+f"(c[2]), "+f"(c[3])
        : "r"(a0), "r"(a1), "r"(a2), "r"(a3), "r"(b0), "r"(b1));
}

// ===== inner attention v4: dense lane packing =================================
// Block = 544 threads (17 warps); thread i -> group gid=i/17 (32 groups/block),
// position p=i%17.  Every lane active: warp-instruction count / 1.88 vs v3.
// Group = (unit, head); k/v staged in block smem [32][17][16] (k[0..5], v[8..15]),
// vector STS/LDS throughout.  Math identical to v3 (rel_err preserved).
__global__ void __launch_bounds__(544)
inner_attn_kernel(const float* __restrict__ x,
                  const float* __restrict__ iwq, const float* __restrict__ ibq,
                  const float* __restrict__ iwk, const float* __restrict__ ibk,
                  const float* __restrict__ iwv, const float* __restrict__ ibv)
{
    __shared__ float swq[HH * D_INN * DKQ_I];   // 72
    __shared__ float sbq[HH * DKQ_I];           // 24
    __shared__ float swk[HH * D_INN * DKQ_I];   // 72
    __shared__ float sbk[HH * DKQ_I];           // 24
    __shared__ float swv[HH * D_INN * DV_I];    // 96
    __shared__ float sbv[HH * DV_I];            // 32
    __shared__ __align__(16) float skv[32][S_IN][16];   // k[0..5], v[8..15]

    const int tid = threadIdx.x;

    // stage weights (independent range checks)
    if (tid < 72)                      swq[tid]        = iwq[tid];
    else if (tid < 144)                swk[tid - 72]   = iwk[tid - 72];
    else if (tid < 240)                swv[tid - 144]  = iwv[tid - 144];
    if (tid < 24)                      sbq[tid]        = ibq[tid];
    else if (tid < 48)                 sbk[tid - 24]   = ibk[tid - 24];
    else if (tid < 80)                 sbv[tid - 48]   = ibv[tid - 48];

    // thread -> (group, position): gid = tid/17 via mul-shift (exact for tid<1028)
    const int gid = (int)(((unsigned)tid * 61681u) >> 20);
    const int p   = tid - gid * 17;
    const int g   = blockIdx.x * 32 + gid;      // global group
    const int u   = g >> 2;
    const int h   = g & 3;

    const float* wqh = swq + h * (D_INN * DKQ_I);
    const float* wkh = swk + h * (D_INN * DKQ_I);
    const float* wvh = swv + h * (D_INN * DV_I);
    const float* bqh = sbq + h * DKQ_I;
    const float* bkh = sbk + h * DKQ_I;
    const float* bvh = sbv + h * DV_I;

    const float scale = 0.40824829046386302f;   // 1/sqrt(6), folded into q

    __syncthreads();                             // weights staged

    float q[DKQ_I];
    {
        const float* xp = x + ((size_t)u * S_IN + p) * D_INN;
        float x0 = xp[0], x1 = xp[1], x2 = xp[2];
        float k[DKQ_I], v[DV_I];
        #pragma unroll
        for (int c = 0; c < DKQ_I; c++) {
            float s = bqh[c] + x0 * wqh[0 * DKQ_I + c] + x1 * wqh[1 * DKQ_I + c]
                             + x2 * wqh[2 * DKQ_I + c];
            q[c] = s * scale;
            k[c] = bkh[c] + x0 * wkh[0 * DKQ_I + c] + x1 * wkh[1 * DKQ_I + c]
                          + x2 * wkh[2 * DKQ_I + c];
        }
        #pragma unroll
        for (int c = 0; c < DV_I; c++) {
            v[c] = bvh[c] + x0 * wvh[0 * DV_I + c] + x1 * wvh[1 * DV_I + c]
                          + x2 * wvh[2 * DV_I + c];
        }
        float* row = &skv[gid][p][0];
        *reinterpret_cast<float4*>(row)     = make_float4(k[0], k[1], k[2], k[3]);
        *reinterpret_cast<float2*>(row + 4) = make_float2(k[4], k[5]);
        *reinterpret_cast<float4*>(row + 8)  = make_float4(v[0], v[1], v[2], v[3]);
        *reinterpret_cast<float4*>(row + 12) = make_float4(v[4], v[5], v[6], v[7]);
    }
    __syncthreads();                             // k/v tiles complete

    {
        // scores vs all 17 keys (vector LDS; lanes of same group broadcast)
        float s[S_IN];
        #pragma unroll
        for (int j = 0; j < S_IN; j++) {
            const float* row = &skv[gid][j][0];
            float4 kA = *reinterpret_cast<const float4*>(row);
            float2 kB = *reinterpret_cast<const float2*>(row + 4);
            s[j] = q[0] * kA.x + q[1] * kA.y + q[2] * kA.z + q[3] * kA.w
                 + q[4] * kB.x + q[5] * kB.y;
        }
        // softmax (normalization folded into context scale)
        float m = s[0];
        #pragma unroll
        for (int j = 1; j < S_IN; j++) m = fmaxf(m, s[j]);
        float sum = 0.f;
        #pragma unroll
        for (int j = 0; j < S_IN; j++) { s[j] = __expf(s[j] - m); sum += s[j]; }
        float inv = 1.f / sum;
        // context (vector LDS)
        float c0 = 0.f, c1 = 0.f, c2 = 0.f, c3 = 0.f;
        float c4 = 0.f, c5 = 0.f, c6 = 0.f, c7 = 0.f;
        #pragma unroll
        for (int j = 0; j < S_IN; j++) {
            const float* row = &skv[gid][j][0];
            float4 v0 = *reinterpret_cast<const float4*>(row + 8);
            float4 v1 = *reinterpret_cast<const float4*>(row + 12);
            float a = s[j];
            c0 += a * v0.x; c1 += a * v0.y; c2 += a * v0.z; c3 += a * v0.w;
            c4 += a * v1.x; c5 += a * v1.y; c6 += a * v1.z; c7 += a * v1.w;
        }
        float4 o0, o1;
        o0.x = rnd_tf32(c0 * inv); o0.y = rnd_tf32(c1 * inv);
        o0.z = rnd_tf32(c2 * inv); o0.w = rnd_tf32(c3 * inv);
        o1.x = rnd_tf32(c4 * inv); o1.y = rnd_tf32(c5 * inv);
        o1.z = rnd_tf32(c6 * inv); o1.w = rnd_tf32(c7 * inv);
        float* op = g_ctx + (size_t)u * CTXI_PER_U + h * (S_IN * DV_I) + p * DV_I;
        *reinterpret_cast<float4*>(op)     = o0;
        *reinterpret_cast<float4*>(op + 4) = o1;
    }
}

// ---------------- weight transpose + tf32 round: W[K][N] -> Wt[N][K] ----------
__global__ void transpose_round(const float* __restrict__ W, float* __restrict__ Wt,
                                int K, int N)
{
    __shared__ float t[32][33];
    int kb = blockIdx.y * 32, nb = blockIdx.x * 32;
    int x = threadIdx.x, y = threadIdx.y;   // 32 x 8
    #pragma unroll
    for (int dy = 0; dy < 32; dy += 8) {
        int k = kb + y + dy, n = nb + x;
        t[y + dy][x] = (k < K && n < N) ? W[(size_t)k * N + n] : 0.f;
    }
    __syncthreads();
    #pragma unroll
    for (int dy = 0; dy < 32; dy += 8) {
        int n = nb + y + dy, k = kb + x;
        if (n < N && k < K) Wt[(size_t)n * K + k] = rnd_tf32(t[x][y + dy]);
    }
}

// ---------------- pack outer qkv weights transposed [768][64] + bias ----------
__global__ void pack_qkv(const float* __restrict__ owq, const float* __restrict__ owk,
                         const float* __restrict__ owv,
                         const float* __restrict__ obq, const float* __restrict__ obk,
                         const float* __restrict__ obv)
{
    int i = blockIdx.x * blockDim.x + threadIdx.x;
    if (i < 768 * 64) {
        int col = i / 64, k = i % 64;
        int sel = col >> 8, hd = col & 255;
        int h = hd >> 6, d = hd & 63;
        const float* w = (sel == 0) ? owq : (sel == 1) ? owk : owv;
        g_wpackT[i] = rnd_tf32(w[(h * 64 + k) * 64 + d]);
    }
    if (i < 768) {
        int sel = i >> 8, hd = i & 255;
        int h = hd >> 6, d = hd & 63;
        const float* b = (sel == 0) ? obq : (sel == 1) ? obk : obv;
        g_bpack[i] = b[h * 64 + d];
    }
}

// ---------------- outer attention: 1 block per (b,h), vectorized -------------
__global__ void outer_attn_kernel()
{
    const int bh = blockIdx.x;         // b*4+h
    const int b  = bh >> 2, h = bh & 3;
    const int tid = threadIdx.x;       // 128

    __shared__ __align__(16) float sq[S_OUT][68], sk[S_OUT][68], sv[S_OUT][68];
    __shared__ float ss[S_OUT][S_OUT];

    for (int i = tid; i < S_OUT * 64; i += blockDim.x) {
        int p = i >> 6, d = i & 63;
        size_t base = (size_t)(b * S_OUT + p) * 768;
        sq[p][d] = g_qkv[base +        h * 64 + d];
        sk[p][d] = g_qkv[base + 256 +  h * 64 + d];
        sv[p][d] = g_qkv[base + 512 +  h * 64 + d];
    }
    __syncthreads();

    for (int i = tid; i < S_OUT * S_OUT; i += blockDim.x) {
        int p = i / S_OUT, j = i % S_OUT;
        const float4* a = reinterpret_cast<const float4*>(&sq[p][0]);
        const float4* bb = reinterpret_cast<const float4*>(&sk[j][0]);
        float s = 0.f;
        #pragma unroll
        for (int c = 0; c < 16; c++) {
            float4 av = a[c], bv = bb[c];
            s += av.x * bv.x + av.y * bv.y + av.z * bv.z + av.w * bv.w;
        }
        ss[p][j] = s * 0.125f;          // 1/sqrt(64)
    }
    __syncthreads();

    if (tid < S_OUT) {
        int p = tid;
        float m = -1e30f;
        #pragma unroll
        for (int j = 0; j < S_OUT; j++) m = fmaxf(m, ss[p][j]);
        float sum = 0.f;
        #pragma unroll
        for (int j = 0; j < S_OUT; j++) { float e = __expf(ss[p][j] - m); ss[p][j] = e; sum += e; }
        float inv = 1.f / sum;
        #pragma unroll
        for (int j = 0; j < S_OUT; j++) ss[p][j] *= inv;
    }
    __syncthreads();

    float* op = g_ctxo + (size_t)bh * (S_OUT * 64);
    for (int i = tid; i < S_OUT * 64; i += blockDim.x) {
        int p = i >> 6, c = i & 63;
        float s = 0.f;
        #pragma unroll
        for (int j = 0; j < S_OUT; j++) s += ss[p][j] * sv[j][c];
        op[i] = rnd_tf32(s);
    }
}

// ===== tf32 mma.sync GEMM, 128 x NT block, 8 warps as 2m x 4n (64 x NT/4) =====
// C = act(A[M,K] @ Bt[N,K]^T + bias).  BK=16, 3-stage cp.async ring, single
// barrier per iteration.  k-slot permutation -> all fragment loads LDS.128,
// chunk XOR swizzle c^(row&3) conflict-free.
// Split-K: gridDim.z slices of k_slice; PART=1 stores raw partials to
// C + z*M*N (no bias/act).  Requires M%128==0, K%4==0, N even, k_slice%16==0.
template<int NT, int ACT, int ROUND, int PART>
__global__ void __launch_bounds__(256, 2)
gemm_mma(const float* __restrict__ A, const float* __restrict__ Bt,
         const float* __restrict__ bias, float* __restrict__ C,
         int M, int N, int K, int k_slice)
{
    constexpr int NSUB = NT / 32;          // B n-subtiles per warp (4 or 2)
    __shared__ float As[3][128][16];
    __shared__ float Bs[3][NT][16];

    const int tid  = threadIdx.x;
    const int warp = tid >> 5, lane = tid & 31;
    const int g = lane >> 2, t = lane & 3;
    const int bm = blockIdx.y * 128, bn = blockIdx.x * NT;
    const int wm = (warp & 1) * 64;                 // warp m offset (64 rows)
    const int wn = (warp >> 1) * (NT / 4);          // warp n offset
    const int kb = blockIdx.z * k_slice;
    const int kend = min(kb + k_slice, K);
    const int niter = (kend - kb + 15) / 16;

    const uint32_t sA = smem_u32(&As[0][0][0]);
    const uint32_t sB = smem_u32(&Bs[0][0][0]);

    auto fill = [&](int i) {
        const int s = i % 3, k0 = kb + i * 16;
        #pragma unroll
        for (int c2 = tid; c2 < 512; c2 += 256) {      // A: 128 rows x 4 chunks
            int r = c2 >> 2, c = c2 & 3;
            int koff = k0 + c * 4;
            int ok = koff < kend;
            cp16(sA + (((s * 128 + r) * 16 + ((c ^ (r & 3)) << 2)) << 2),
                 A + (size_t)(bm + r) * K + (ok ? koff : 0), ok ? 16 : 0);
        }
        #pragma unroll
        for (int c2 = tid; c2 < NT * 4; c2 += 256) {   // B: NT rows x 4 chunks
            int r = c2 >> 2, c = c2 & 3;
            int koff = k0 + c * 4;
            int n = bn + r;
            int ok = (n < N) && (koff < kend);
            cp16(sB + (((s * NT + r) * 16 + ((c ^ (r & 3)) << 2)) << 2),
                 Bt + (size_t)(ok ? n : 0) * K + (ok ? koff : 0), ok ? 16 : 0);
        }
        cp_commit();
    };

    float acc[4][NSUB][4] = {};

    fill(0);
    if (niter > 1) fill(1);

    for (int i = 0; i < niter; i++) {
        const int s = i % 3;
        if (i + 1 < niter) cp_wait<1>(); else cp_wait<0>();
        __syncthreads();
        if (i + 2 < niter) fill(i + 2);    // buffer (i+2)%3 free since iter i-1

        float4 alo[4], ahi[4], bf[NSUB];
        #pragma unroll
        for (int mt = 0; mt < 4; mt++) {
            int r0 = wm + mt * 16 + g, r1 = r0 + 8;
            alo[mt] = *reinterpret_cast<const float4*>(&As[s][r0][(t ^ (r0 & 3)) << 2]);
            ahi[mt] = *reinterpret_cast<const float4*>(&As[s][r1][(t ^ (r1 & 3)) << 2]);
        }
        #pragma unroll
        for (int nt = 0; nt < NSUB; nt++) {
            int n = wn + nt * 8 + g;
            bf[nt] = *reinterpret_cast<const float4*>(&Bs[s][n][(t ^ (n & 3)) << 2]);
        }
        #pragma unroll
        for (int mt = 0; mt < 4; mt++)
            #pragma unroll
            for (int nt = 0; nt < NSUB; nt++) {
                mma_tf32(acc[mt][nt],
                         __float_as_uint(alo[mt].x), __float_as_uint(ahi[mt].x),
                         __float_as_uint(alo[mt].y), __float_as_uint(ahi[mt].y),
                         __float_as_uint(bf[nt].x),  __float_as_uint(bf[nt].y));
                mma_tf32(acc[mt][nt],
                         __float_as_uint(alo[mt].z), __float_as_uint(ahi[mt].z),
                         __float_as_uint(alo[mt].w), __float_as_uint(ahi[mt].w),
                         __float_as_uint(bf[nt].z),  __float_as_uint(bf[nt].w));
            }
    }

    // epilogue: acc[mt][nt] -> rows (g, g+8), cols (2t, 2t+1)
    float* Cz = PART ? (C + (size_t)blockIdx.z * M * N) : C;
    #pragma unroll
    for (int mt = 0; mt < 4; mt++) {
        #pragma unroll
        for (int nt = 0; nt < NSUB; nt++) {
            int row0 = bm + wm + mt * 16 + g;
            int col  = bn + wn + nt * 8 + 2 * t;
            if (col >= N) continue;
            float b0 = PART ? 0.f : bias[col];
            float b1 = PART ? 0.f : bias[col + 1];
            #pragma unroll
            for (int half = 0; half < 2; half++) {
                int r = row0 + half * 8;
                float2 v;
                v.x = acc[mt][nt][half * 2 + 0] + b0;
                v.y = acc[mt][nt][half * 2 + 1] + b1;
                if (!PART && ACT)   { v.x = tanh_fast(v.x); v.y = tanh_fast(v.y); }
                if (!PART && ROUND) { v.x = rnd_tf32(v.x);  v.y = rnd_tf32(v.y); }
                *reinterpret_cast<float2*>(Cz + (size_t)r * N + col) = v;
            }
        }
    }
}

// ---------------- split-K reduce: out = sum_s part[s] + bias ------------------
template<int S>
__global__ void reduce_splitk(const float* __restrict__ part, const float* __restrict__ bias,
                              float* __restrict__ out, int M, int N)
{
    int idx = blockIdx.x * blockDim.x + threadIdx.x;
    if (idx >= M * N) return;
    int n = idx % N;
    float s = bias[n];
    #pragma unroll
    for (int i = 0; i < S; i++) s += part[(size_t)i * M * N + idx];
    out[idx] = s;
}

static inline int cdiv(int a, int b) { return (a + b - 1) / b; }

extern "C" void kernel_launch(void* const* d_in, const int* in_sizes, int n_in,
                              void* d_out, int out_size)
{
    (void)in_sizes; (void)n_in; (void)out_size;
    const float* x   = (const float*)d_in[0];
    const float* iwq = (const float*)d_in[1];
    const float* ibq = (const float*)d_in[2];
    const float* iwk = (const float*)d_in[3];
    const float* ibk = (const float*)d_in[4];
    const float* iwv = (const float*)d_in[5];
    const float* ibv = (const float*)d_in[6];
    const float* iw1 = (const float*)d_in[7];
    const float* ib1 = (const float*)d_in[8];
    const float* iw2 = (const float*)d_in[9];
    const float* ib2 = (const float*)d_in[10];
    const float* owq = (const float*)d_in[11];
    const float* obq = (const float*)d_in[12];
    const float* owk = (const float*)d_in[13];
    const float* obk = (const float*)d_in[14];
    const float* owv = (const float*)d_in[15];
    const float* obv = (const float*)d_in[16];
    const float* ow1 = (const float*)d_in[17];
    const float* ob1 = (const float*)d_in[18];
    const float* ow2 = (const float*)d_in[19];
    const float* ob2 = (const float*)d_in[20];
    float* out = (float*)d_out;

    float *p_ctx, *p_h1, *p_seq, *p_wpT, *p_bp, *p_qkv, *p_ctxo, *p_h2, *p_part;
    float *p_w1t, *p_w2t, *p_w3t, *p_w4t;
    cudaGetSymbolAddress((void**)&p_ctx,  g_ctx);
    cudaGetSymbolAddress((void**)&p_h1,   g_h1);
    cudaGetSymbolAddress((void**)&p_seq,  g_seq);
    cudaGetSymbolAddress((void**)&p_wpT,  g_wpackT);
    cudaGetSymbolAddress((void**)&p_bp,   g_bpack);
    cudaGetSymbolAddress((void**)&p_qkv,  g_qkv);
    cudaGetSymbolAddress((void**)&p_ctxo, g_ctxo);
    cudaGetSymbolAddress((void**)&p_h2,   g_h2);
    cudaGetSymbolAddress((void**)&p_part, g_part);
    cudaGetSymbolAddress((void**)&p_w1t,  g_w1t);
    cudaGetSymbolAddress((void**)&p_w2t,  g_w2t);
    cudaGetSymbolAddress((void**)&p_w3t,  g_w3t);
    cudaGetSymbolAddress((void**)&p_w4t,  g_w4t);

    // 0,1,2) weight transposes + qkv pack (independent of data path)
    transpose_round<<<dim3(cdiv(256, 32),  cdiv(136, 32)),  dim3(32, 8)>>>(iw1, p_w1t, 136, 256);
    transpose_round<<<dim3(cdiv(64, 32),   cdiv(1024, 32)), dim3(32, 8)>>>(iw2, p_w2t, 1024, 64);
    pack_qkv<<<cdiv(768 * 64, 256), 256>>>(owq, owk, owv, obq, obk, obv);

    // 3) inner attention v4 -> g_ctx [122880][136]   (ncu capture slot)
    inner_attn_kernel<<<FC1I_M / 32, 544>>>(x, iwq, ibq, iwk, ibk, iwv, ibv);

    // 4) fc1_i: [122880,136] @ w1t[256,136]^T + tanh -> g_h1
    gemm_mma<128, 1, 1, 0><<<dim3(2, FC1I_M / 128), 256>>>(
        p_ctx, p_w1t, ib1, p_h1, FC1I_M, 256, 136, 136);

    // 5) fc2_i: [30720,1024] @ w2t[64,1024]^T -> g_seq
    gemm_mma<64, 0, 1, 0><<<dim3(1, NU / 128), 256>>>(
        p_h1, p_w2t, ib2, p_seq, NU, 64, 1024, 1024);

    // 6) outer qkv: [30720,64] @ wpackT[768,64]^T -> g_qkv
    gemm_mma<128, 0, 0, 0><<<dim3(6, NU / 128), 256>>>(
        p_seq, p_wpT, p_bp, p_qkv, NU, 768, 64, 64);

    // 7) outer attention -> g_ctxo [4096][1920] (rounded)
    outer_attn_kernel<<<BB * HH, 128>>>();

    // 8,9) transposes for outer GEMMs
    transpose_round<<<dim3(cdiv(1024, 32), cdiv(1920, 32)), dim3(32, 8)>>>(ow1, p_w3t, 1920, 1024);
    transpose_round<<<dim3(cdiv(1080, 32), cdiv(4096, 32)), dim3(32, 8)>>>(ow2, p_w4t, 4096, 1080);

    // 10) fc1_o: [4096,1920] @ w3t[1024,1920]^T + tanh -> g_h2  (256 CTAs)
    gemm_mma<128, 1, 1, 0><<<dim3(8, (BB * HH) / 128), 256>>>(
        p_ctxo, p_w3t, ob1, p_h2, BB * HH, 1024, 1920, 1920);

    // 11) fc2_o split-K=4: [1024,4096] @ w4t[1080,4096]^T -> partials (288 CTAs)
    gemm_mma<128, 0, 0, 1><<<dim3(cdiv(OUT_O, 128), BB / 128, 4), 256>>>(
        p_h2, p_w4t, nullptr, p_part, BB, OUT_O, HH * HID_O, 1024);

    // 12) reduce partials + bias -> out
    reduce_splitk<4><<<cdiv(BB * OUT_O, 256), 256>>>(p_part, ob2, out, BB, OUT_O);
}

// round 16
// speedup vs baseline: 1.5777x; 1.5777x over previous
#include <cuda_runtime.h>
#include <cuda_bf16.h>
#include <cstdint>

// ---------------- problem constants ----------------
#define BB      1024
#define S_OUT   30
#define S_IN    17
#define D_INN   3
#define HH      4
#define DKQ_I   6
#define DV_I    8
#define HID_I   256
#define OUT_I   64
#define HID_O   1024
#define OUT_O   1080

#define NU      (BB * S_OUT)          // 30720 inner units
#define CTXI_PER_U (HH * S_IN * DV_I) // 544
#define FC1I_M  (NU * HH)             // 122880
#define FC1I_K  (S_IN * DV_I)         // 136

// ---------------- scratch (device globals; no runtime allocation) -------------
__device__ float g_ctx  [(size_t)NU * CTXI_PER_U + 64];   // [122880][136]
__device__ float g_h1   [(size_t)FC1I_M * HID_I];         // [30720][1024]
__device__ float g_seq  [(size_t)NU * 64];                // [30720][64]
__device__ float g_wpackT[768 * 64];                      // [n=768][k=64] rounded
__device__ float g_bpack[768];
__device__ float g_qkv  [(size_t)NU * 768];               // [30720][768]
__device__ float g_ctxo [(size_t)BB * HH * S_OUT * 64];   // [4096][1920]
__device__ float g_h2   [(size_t)BB * HH * HID_O];        // [1024][4096]
__device__ float g_part [(size_t)4 * BB * OUT_O];         // split-K partials fc2_o
// transposed + tf32-rounded weights ([N][K])
__device__ float g_w1t[256 * 136];
__device__ float g_w2t[64 * 1024];
__device__ float g_w3t[1024 * 1920];
__device__ float g_w4t[1080 * 4096];

// ---------------- helpers ----------------
__device__ __forceinline__ float tanh_fast(float x) {
    float y; asm("tanh.approx.f32 %0, %1;" : "=f"(y) : "f"(x)); return y;
}
// round fp32 -> tf32 precision (RNA when followed by HW truncation of low 13 bits)
__device__ __forceinline__ float rnd_tf32(float f) {
    return __uint_as_float(__float_as_uint(f) + 0x1000u);
}
__device__ __forceinline__ uint32_t smem_u32(const void* p) {
    uint32_t a;
    asm("{ .reg .u64 t; cvta.to.shared.u64 t, %1; cvt.u32.u64 %0, t; }" : "=r"(a) : "l"(p));
    return a;
}
__device__ __forceinline__ void cp16(uint32_t dst, const void* src, int sz) {
    asm volatile("cp.async.cg.shared.global [%0], [%1], 16, %2;"
                 :: "r"(dst), "l"(src), "r"(sz) : "memory");
}
__device__ __forceinline__ void cp_commit() {
    asm volatile("cp.async.commit_group;" ::: "memory");
}
template<int N> __device__ __forceinline__ void cp_wait() {
    asm volatile("cp.async.wait_group %0;" :: "n"(N) : "memory");
}
__device__ __forceinline__ void mma_tf32(float c[4], uint32_t a0, uint32_t a1,
                                         uint32_t a2, uint32_t a3,
                                         uint32_t b0, uint32_t b1) {
    asm volatile(
        "mma.sync.aligned.m16n8k8.row.col.f32.tf32.tf32.f32 "
        "{%0,%1,%2,%3}, {%4,%5,%6,%7}, {%8,%9}, {%0,%1,%2,%3};"
        : "+f"(c[0]), "+f"(c[1]), "+f"(c[2]), "+f"(c[3])
        : "r"(a0), "r"(a1), "r"(a2), "r"(a3), "r"(b0), "r"(b1));
}

// ===== inner attention v3 (reverted from failed v4): 1 warp per (unit, head) ==
// skv rows padded to 20 floats (80B, 16B-aligned): k in [0..5], v in [8..15].
// All k/v exchange via vector STS/LDS; 17 active lanes per warp share the same
// row address per j -> broadcast wavefronts (the property v4 broke).
__global__ void __launch_bounds__(256)
inner_attn_kernel(const float* __restrict__ x,
                  const float* __restrict__ iwq, const float* __restrict__ ibq,
                  const float* __restrict__ iwk, const float* __restrict__ ibk,
                  const float* __restrict__ iwv, const float* __restrict__ ibv)
{
    __shared__ float swq[HH * D_INN * DKQ_I];   // 72
    __shared__ float sbq[HH * DKQ_I];           // 24
    __shared__ float swk[HH * D_INN * DKQ_I];   // 72
    __shared__ float sbk[HH * DKQ_I];           // 24
    __shared__ float swv[HH * D_INN * DV_I];    // 96
    __shared__ float sbv[HH * DV_I];            // 32
    __shared__ __align__(16) float skv[8][S_IN][20];   // k[0..5], v[8..15]

    const int tid = threadIdx.x;

    // stage weights (independent range checks)
    if (tid < 72)                      swq[tid]        = iwq[tid];
    else if (tid < 144)                swk[tid - 72]   = iwk[tid - 72];
    else if (tid < 240)                swv[tid - 144]  = iwv[tid - 144];
    if (tid < 24)                      sbq[tid]        = ibq[tid];
    else if (tid < 48)                 sbk[tid - 24]   = ibk[tid - 24];
    else if (tid < 80)                 sbv[tid - 48]   = ibv[tid - 48];
    __syncthreads();

    const int w    = tid >> 5;
    const int lane = tid & 31;
    const int u    = blockIdx.x * 2 + (w >> 2);
    const int h    = w & 3;

    const float* wqh = swq + h * (D_INN * DKQ_I);
    const float* wkh = swk + h * (D_INN * DKQ_I);
    const float* wvh = swv + h * (D_INN * DV_I);
    const float* bqh = sbq + h * DKQ_I;
    const float* bkh = sbk + h * DKQ_I;
    const float* bvh = sbv + h * DV_I;

    const float scale = 0.40824829046386302f;   // 1/sqrt(6), folded into q

    float q[DKQ_I];
    if (lane < S_IN) {
        const float* xp = x + ((size_t)u * S_IN + lane) * D_INN;
        float x0 = xp[0], x1 = xp[1], x2 = xp[2];
        float k[DKQ_I], v[DV_I];
        #pragma unroll
        for (int c = 0; c < DKQ_I; c++) {
            float s = bqh[c] + x0 * wqh[0 * DKQ_I + c] + x1 * wqh[1 * DKQ_I + c]
                             + x2 * wqh[2 * DKQ_I + c];
            q[c] = s * scale;
            k[c] = bkh[c] + x0 * wkh[0 * DKQ_I + c] + x1 * wkh[1 * DKQ_I + c]
                          + x2 * wkh[2 * DKQ_I + c];
        }
        #pragma unroll
        for (int c = 0; c < DV_I; c++) {
            v[c] = bvh[c] + x0 * wvh[0 * DV_I + c] + x1 * wvh[1 * DV_I + c]
                          + x2 * wvh[2 * DV_I + c];
        }
        float* row = &skv[w][lane][0];
        *reinterpret_cast<float4*>(row)     = make_float4(k[0], k[1], k[2], k[3]);
        *reinterpret_cast<float2*>(row + 4) = make_float2(k[4], k[5]);
        *reinterpret_cast<float4*>(row + 8)  = make_float4(v[0], v[1], v[2], v[3]);
        *reinterpret_cast<float4*>(row + 12) = make_float4(v[4], v[5], v[6], v[7]);
    }
    __syncwarp();

    if (lane < S_IN) {
        // scores vs all 17 keys (vector broadcast LDS)
        float s[S_IN];
        #pragma unroll
        for (int j = 0; j < S_IN; j++) {
            const float* row = &skv[w][j][0];
            float4 kA = *reinterpret_cast<const float4*>(row);
            float2 kB = *reinterpret_cast<const float2*>(row + 4);
            s[j] = q[0] * kA.x + q[1] * kA.y + q[2] * kA.z + q[3] * kA.w
                 + q[4] * kB.x + q[5] * kB.y;
        }
        // softmax (normalization folded into context scale)
        float m = s[0];
        #pragma unroll
        for (int j = 1; j < S_IN; j++) m = fmaxf(m, s[j]);
        float sum = 0.f;
        #pragma unroll
        for (int j = 0; j < S_IN; j++) { s[j] = __expf(s[j] - m); sum += s[j]; }
        float inv = 1.f / sum;
        // context (vector broadcast LDS)
        float c0 = 0.f, c1 = 0.f, c2 = 0.f, c3 = 0.f;
        float c4 = 0.f, c5 = 0.f, c6 = 0.f, c7 = 0.f;
        #pragma unroll
        for (int j = 0; j < S_IN; j++) {
            const float* row = &skv[w][j][0];
            float4 v0 = *reinterpret_cast<const float4*>(row + 8);
            float4 v1 = *reinterpret_cast<const float4*>(row + 12);
            float a = s[j];
            c0 += a * v0.x; c1 += a * v0.y; c2 += a * v0.z; c3 += a * v0.w;
            c4 += a * v1.x; c5 += a * v1.y; c6 += a * v1.z; c7 += a * v1.w;
        }
        float4 o0, o1;
        o0.x = rnd_tf32(c0 * inv); o0.y = rnd_tf32(c1 * inv);
        o0.z = rnd_tf32(c2 * inv); o0.w = rnd_tf32(c3 * inv);
        o1.x = rnd_tf32(c4 * inv); o1.y = rnd_tf32(c5 * inv);
        o1.z = rnd_tf32(c6 * inv); o1.w = rnd_tf32(c7 * inv);
        float* op = g_ctx + (size_t)u * CTXI_PER_U + h * (S_IN * DV_I) + lane * DV_I;
        *reinterpret_cast<float4*>(op)     = o0;
        *reinterpret_cast<float4*>(op + 4) = o1;
    }
}

// ---------------- weight transpose + tf32 round: W[K][N] -> Wt[N][K] ----------
__global__ void transpose_round(const float* __restrict__ W, float* __restrict__ Wt,
                                int K, int N)
{
    __shared__ float t[32][33];
    int kb = blockIdx.y * 32, nb = blockIdx.x * 32;
    int x = threadIdx.x, y = threadIdx.y;   // 32 x 8
    #pragma unroll
    for (int dy = 0; dy < 32; dy += 8) {
        int k = kb + y + dy, n = nb + x;
        t[y + dy][x] = (k < K && n < N) ? W[(size_t)k * N + n] : 0.f;
    }
    __syncthreads();
    #pragma unroll
    for (int dy = 0; dy < 32; dy += 8) {
        int n = nb + y + dy, k = kb + x;
        if (n < N && k < K) Wt[(size_t)n * K + k] = rnd_tf32(t[x][y + dy]);
    }
}

// ---------------- pack outer qkv weights transposed [768][64] + bias ----------
__global__ void pack_qkv(const float* __restrict__ owq, const float* __restrict__ owk,
                         const float* __restrict__ owv,
                         const float* __restrict__ obq, const float* __restrict__ obk,
                         const float* __restrict__ obv)
{
    int i = blockIdx.x * blockDim.x + threadIdx.x;
    if (i < 768 * 64) {
        int col = i / 64, k = i % 64;
        int sel = col >> 8, hd = col & 255;
        int h = hd >> 6, d = hd & 63;
        const float* w = (sel == 0) ? owq : (sel == 1) ? owk : owv;
        g_wpackT[i] = rnd_tf32(w[(h * 64 + k) * 64 + d]);
    }
    if (i < 768) {
        int sel = i >> 8, hd = i & 255;
        int h = hd >> 6, d = hd & 63;
        const float* b = (sel == 0) ? obq : (sel == 1) ? obk : obv;
        g_bpack[i] = b[h * 64 + d];
    }
}

// ---------------- outer attention: 1 block per (b,h), fully vectorized --------
__global__ void outer_attn_kernel()
{
    const int bh = blockIdx.x;         // b*4+h
    const int b  = bh >> 2, h = bh & 3;
    const int tid = threadIdx.x;       // 128

    __shared__ __align__(16) float sq[S_OUT][68], sk[S_OUT][68], sv[S_OUT][68];
    __shared__ float ss[S_OUT][S_OUT];

    // loads: float4 per element group (3 vector LDG per 4 scalars)
    for (int i = tid; i < S_OUT * 16; i += blockDim.x) {
        int p = i >> 4, d4 = (i & 15) * 4;
        const float* base = g_qkv + (size_t)(b * S_OUT + p) * 768 + h * 64 + d4;
        *reinterpret_cast<float4*>(&sq[p][d4]) = *reinterpret_cast<const float4*>(base);
        *reinterpret_cast<float4*>(&sk[p][d4]) = *reinterpret_cast<const float4*>(base + 256);
        *reinterpret_cast<float4*>(&sv[p][d4]) = *reinterpret_cast<const float4*>(base + 512);
    }
    __syncthreads();

    for (int i = tid; i < S_OUT * S_OUT; i += blockDim.x) {
        int p = i / S_OUT, j = i % S_OUT;
        const float4* a = reinterpret_cast<const float4*>(&sq[p][0]);
        const float4* bb = reinterpret_cast<const float4*>(&sk[j][0]);
        float s = 0.f;
        #pragma unroll
        for (int c = 0; c < 16; c++) {
            float4 av = a[c], bv = bb[c];
            s += av.x * bv.x + av.y * bv.y + av.z * bv.z + av.w * bv.w;
        }
        ss[p][j] = s * 0.125f;          // 1/sqrt(64)
    }
    __syncthreads();

    if (tid < S_OUT) {
        int p = tid;
        float m = -1e30f;
        #pragma unroll
        for (int j = 0; j < S_OUT; j++) m = fmaxf(m, ss[p][j]);
        float sum = 0.f;
        #pragma unroll
        for (int j = 0; j < S_OUT; j++) { float e = __expf(ss[p][j] - m); ss[p][j] = e; sum += e; }
        float inv = 1.f / sum;
        #pragma unroll
        for (int j = 0; j < S_OUT; j++) ss[p][j] *= inv;
    }
    __syncthreads();

    // context: each item = (p, 4 consecutive cols); one float4 row read per j
    float* op = g_ctxo + (size_t)bh * (S_OUT * 64);
    for (int i = tid; i < S_OUT * 16; i += blockDim.x) {
        int p = i >> 4, c4 = (i & 15) * 4;
        float a0 = 0.f, a1 = 0.f, a2 = 0.f, a3 = 0.f;
        #pragma unroll
        for (int j = 0; j < S_OUT; j++) {
            float w = ss[p][j];
            float4 vv = *reinterpret_cast<const float4*>(&sv[j][c4]);
            a0 += w * vv.x; a1 += w * vv.y; a2 += w * vv.z; a3 += w * vv.w;
        }
        float4 o;
        o.x = rnd_tf32(a0); o.y = rnd_tf32(a1); o.z = rnd_tf32(a2); o.w = rnd_tf32(a3);
        *reinterpret_cast<float4*>(op + p * 64 + c4) = o;
    }
}

// ===== tf32 mma.sync GEMM, 128 x NT block, 8 warps as 2m x 4n (64 x NT/4) =====
// C = act(A[M,K] @ Bt[N,K]^T + bias).  BK=16, 3-stage cp.async ring, single
// barrier per iteration.  k-slot permutation -> all fragment loads LDS.128,
// chunk XOR swizzle c^(row&3) conflict-free.
// Split-K: gridDim.z slices of k_slice; PART=1 stores raw partials to
// C + z*M*N (no bias/act).  Requires M%128==0, K%4==0, N even, k_slice%16==0.
template<int NT, int ACT, int ROUND, int PART>
__global__ void __launch_bounds__(256, 2)
gemm_mma(const float* __restrict__ A, const float* __restrict__ Bt,
         const float* __restrict__ bias, float* __restrict__ C,
         int M, int N, int K, int k_slice)
{
    constexpr int NSUB = NT / 32;          // B n-subtiles per warp (4 or 2)
    __shared__ float As[3][128][16];
    __shared__ float Bs[3][NT][16];

    const int tid  = threadIdx.x;
    const int warp = tid >> 5, lane = tid & 31;
    const int g = lane >> 2, t = lane & 3;
    const int bm = blockIdx.y * 128, bn = blockIdx.x * NT;
    const int wm = (warp & 1) * 64;                 // warp m offset (64 rows)
    const int wn = (warp >> 1) * (NT / 4);          // warp n offset
    const int kb = blockIdx.z * k_slice;
    const int kend = min(kb + k_slice, K);
    const int niter = (kend - kb + 15) / 16;

    const uint32_t sA = smem_u32(&As[0][0][0]);
    const uint32_t sB = smem_u32(&Bs[0][0][0]);

    auto fill = [&](int i) {
        const int s = i % 3, k0 = kb + i * 16;
        #pragma unroll
        for (int c2 = tid; c2 < 512; c2 += 256) {      // A: 128 rows x 4 chunks
            int r = c2 >> 2, c = c2 & 3;
            int koff = k0 + c * 4;
            int ok = koff < kend;
            cp16(sA + (((s * 128 + r) * 16 + ((c ^ (r & 3)) << 2)) << 2),
                 A + (size_t)(bm + r) * K + (ok ? koff : 0), ok ? 16 : 0);
        }
        #pragma unroll
        for (int c2 = tid; c2 < NT * 4; c2 += 256) {   // B: NT rows x 4 chunks
            int r = c2 >> 2, c = c2 & 3;
            int koff = k0 + c * 4;
            int n = bn + r;
            int ok = (n < N) && (koff < kend);
            cp16(sB + (((s * NT + r) * 16 + ((c ^ (r & 3)) << 2)) << 2),
                 Bt + (size_t)(ok ? n : 0) * K + (ok ? koff : 0), ok ? 16 : 0);
        }
        cp_commit();
    };

    float acc[4][NSUB][4] = {};

    fill(0);
    if (niter > 1) fill(1);

    for (int i = 0; i < niter; i++) {
        const int s = i % 3;
        if (i + 1 < niter) cp_wait<1>(); else cp_wait<0>();
        __syncthreads();
        if (i + 2 < niter) fill(i + 2);    // buffer (i+2)%3 free since iter i-1

        float4 alo[4], ahi[4], bf[NSUB];
        #pragma unroll
        for (int mt = 0; mt < 4; mt++) {
            int r0 = wm + mt * 16 + g, r1 = r0 + 8;
            alo[mt] = *reinterpret_cast<const float4*>(&As[s][r0][(t ^ (r0 & 3)) << 2]);
            ahi[mt] = *reinterpret_cast<const float4*>(&As[s][r1][(t ^ (r1 & 3)) << 2]);
        }
        #pragma unroll
        for (int nt = 0; nt < NSUB; nt++) {
            int n = wn + nt * 8 + g;
            bf[nt] = *reinterpret_cast<const float4*>(&Bs[s][n][(t ^ (n & 3)) << 2]);
        }
        #pragma unroll
        for (int mt = 0; mt < 4; mt++)
            #pragma unroll
            for (int nt = 0; nt < NSUB; nt++) {
                mma_tf32(acc[mt][nt],
                         __float_as_uint(alo[mt].x), __float_as_uint(ahi[mt].x),
                         __float_as_uint(alo[mt].y), __float_as_uint(ahi[mt].y),
                         __float_as_uint(bf[nt].x),  __float_as_uint(bf[nt].y));
                mma_tf32(acc[mt][nt],
                         __float_as_uint(alo[mt].z), __float_as_uint(ahi[mt].z),
                         __float_as_uint(alo[mt].w), __float_as_uint(ahi[mt].w),
                         __float_as_uint(bf[nt].z),  __float_as_uint(bf[nt].w));
            }
    }

    // epilogue: acc[mt][nt] -> rows (g, g+8), cols (2t, 2t+1)
    float* Cz = PART ? (C + (size_t)blockIdx.z * M * N) : C;
    #pragma unroll
    for (int mt = 0; mt < 4; mt++) {
        #pragma unroll
        for (int nt = 0; nt < NSUB; nt++) {
            int row0 = bm + wm + mt * 16 + g;
            int col  = bn + wn + nt * 8 + 2 * t;
            if (col >= N) continue;
            float b0 = PART ? 0.f : bias[col];
            float b1 = PART ? 0.f : bias[col + 1];
            #pragma unroll
            for (int half = 0; half < 2; half++) {
                int r = row0 + half * 8;
                float2 v;
                v.x = acc[mt][nt][half * 2 + 0] + b0;
                v.y = acc[mt][nt][half * 2 + 1] + b1;
                if (!PART && ACT)   { v.x = tanh_fast(v.x); v.y = tanh_fast(v.y); }
                if (!PART && ROUND) { v.x = rnd_tf32(v.x);  v.y = rnd_tf32(v.y); }
                *reinterpret_cast<float2*>(Cz + (size_t)r * N + col) = v;
            }
        }
    }
}

// ---------------- split-K reduce: out = sum_s part[s] + bias ------------------
template<int S>
__global__ void reduce_splitk(const float* __restrict__ part, const float* __restrict__ bias,
                              float* __restrict__ out, int M, int N)
{
    int idx = blockIdx.x * blockDim.x + threadIdx.x;
    if (idx >= M * N) return;
    int n = idx % N;
    float s = bias[n];
    #pragma unroll
    for (int i = 0; i < S; i++) s += part[(size_t)i * M * N + idx];
    out[idx] = s;
}

static inline int cdiv(int a, int b) { return (a + b - 1) / b; }

extern "C" void kernel_launch(void* const* d_in, const int* in_sizes, int n_in,
                              void* d_out, int out_size)
{
    (void)in_sizes; (void)n_in; (void)out_size;
    const float* x   = (const float*)d_in[0];
    const float* iwq = (const float*)d_in[1];
    const float* ibq = (const float*)d_in[2];
    const float* iwk = (const float*)d_in[3];
    const float* ibk = (const float*)d_in[4];
    const float* iwv = (const float*)d_in[5];
    const float* ibv = (const float*)d_in[6];
    const float* iw1 = (const float*)d_in[7];
    const float* ib1 = (const float*)d_in[8];
    const float* iw2 = (const float*)d_in[9];
    const float* ib2 = (const float*)d_in[10];
    const float* owq = (const float*)d_in[11];
    const float* obq = (const float*)d_in[12];
    const float* owk = (const float*)d_in[13];
    const float* obk = (const float*)d_in[14];
    const float* owv = (const float*)d_in[15];
    const float* obv = (const float*)d_in[16];
    const float* ow1 = (const float*)d_in[17];
    const float* ob1 = (const float*)d_in[18];
    const float* ow2 = (const float*)d_in[19];
    const float* ob2 = (const float*)d_in[20];
    float* out = (float*)d_out;

    float *p_ctx, *p_h1, *p_seq, *p_wpT, *p_bp, *p_qkv, *p_ctxo, *p_h2, *p_part;
    float *p_w1t, *p_w2t, *p_w3t, *p_w4t;
    cudaGetSymbolAddress((void**)&p_ctx,  g_ctx);
    cudaGetSymbolAddress((void**)&p_h1,   g_h1);
    cudaGetSymbolAddress((void**)&p_seq,  g_seq);
    cudaGetSymbolAddress((void**)&p_wpT,  g_wpackT);
    cudaGetSymbolAddress((void**)&p_bp,   g_bpack);
    cudaGetSymbolAddress((void**)&p_qkv,  g_qkv);
    cudaGetSymbolAddress((void**)&p_ctxo, g_ctxo);
    cudaGetSymbolAddress((void**)&p_h2,   g_h2);
    cudaGetSymbolAddress((void**)&p_part, g_part);
    cudaGetSymbolAddress((void**)&p_w1t,  g_w1t);
    cudaGetSymbolAddress((void**)&p_w2t,  g_w2t);
    cudaGetSymbolAddress((void**)&p_w3t,  g_w3t);
    cudaGetSymbolAddress((void**)&p_w4t,  g_w4t);

    // 0,1,2) weight transposes + qkv pack (independent of data path)
    transpose_round<<<dim3(cdiv(256, 32),  cdiv(136, 32)),  dim3(32, 8)>>>(iw1, p_w1t, 136, 256);
    transpose_round<<<dim3(cdiv(64, 32),   cdiv(1024, 32)), dim3(32, 8)>>>(iw2, p_w2t, 1024, 64);
    pack_qkv<<<cdiv(768 * 64, 256), 256>>>(owq, owk, owv, obq, obk, obv);

    // 3) inner attention v3 -> g_ctx [122880][136]   (ncu capture slot)
    inner_attn_kernel<<<NU / 2, 256>>>(x, iwq, ibq, iwk, ibk, iwv, ibv);

    // 4) fc1_i: [122880,136] @ w1t[256,136]^T + tanh -> g_h1
    gemm_mma<128, 1, 1, 0><<<dim3(2, FC1I_M / 128), 256>>>(
        p_ctx, p_w1t, ib1, p_h1, FC1I_M, 256, 136, 136);

    // 5) fc2_i: [30720,1024] @ w2t[64,1024]^T -> g_seq
    gemm_mma<64, 0, 1, 0><<<dim3(1, NU / 128), 256>>>(
        p_h1, p_w2t, ib2, p_seq, NU, 64, 1024, 1024);

    // 6) outer qkv: [30720,64] @ wpackT[768,64]^T -> g_qkv
    gemm_mma<128, 0, 0, 0><<<dim3(6, NU / 128), 256>>>(
        p_seq, p_wpT, p_bp, p_qkv, NU, 768, 64, 64);

    // 7) outer attention -> g_ctxo [4096][1920] (rounded)
    outer_attn_kernel<<<BB * HH, 128>>>();

    // 8,9) transposes for outer GEMMs
    transpose_round<<<dim3(cdiv(1024, 32), cdiv(1920, 32)), dim3(32, 8)>>>(ow1, p_w3t, 1920, 1024);
    transpose_round<<<dim3(cdiv(1080, 32), cdiv(4096, 32)), dim3(32, 8)>>>(ow2, p_w4t, 4096, 1080);

    // 10) fc1_o: [4096,1920] @ w3t[1024,1920]^T + tanh -> g_h2  (256 CTAs)
    gemm_mma<128, 1, 1, 0><<<dim3(8, (BB * HH) / 128), 256>>>(
        p_ctxo, p_w3t, ob1, p_h2, BB * HH, 1024, 1920, 1920);

    // 11) fc2_o split-K=4: [1024,4096] @ w4t[1080,4096]^T -> partials (288 CTAs)
    gemm_mma<128, 0, 0, 1><<<dim3(cdiv(OUT_O, 128), BB / 128, 4), 256>>>(
        p_h2, p_w4t, nullptr, p_part, BB, OUT_O, HH * HID_O, 1024);

    // 12) reduce partials + bias -> out
    reduce_splitk<4><<<cdiv(BB * OUT_O, 256), 256>>>(p_part, ob2, out, BB, OUT_O);
}